// round 2
// baseline (speedup 1.0000x reference)
#include <cuda_runtime.h>
#include <math.h>
#include <stdint.h>

#define BB 128
#define RR 4608
#define OO 32
#define II 16
#define KO 64
#define NR 16                  // r per CTA
#define NCTA (RR/NR)           // 288
#define INV_B (1.0f/128.0f)
#define INV_R (1.0f/4608.0f)

typedef unsigned long long ull;

// Global scratch
__device__ float g_s0[BB * KO];
__device__ float g_S[2][BB * KO];
__device__ float g_Z[2][2];
__device__ float g_v[2][BB * KO];
__device__ float g_b1[RR * 2];

// ---------------- f32x2 helpers (FFMA2 path, exact fp32) -------------------
__device__ __forceinline__ ull pack2(float lo, float hi) {
    ull r; asm("mov.b64 %0, {%1, %2};" : "=l"(r) : "f"(lo), "f"(hi)); return r;
}
__device__ __forceinline__ void unpack2(ull v, float& lo, float& hi) {
    asm("mov.b64 {%0, %1}, %2;" : "=f"(lo), "=f"(hi) : "l"(v));
}
__device__ __forceinline__ ull fma2(ull a, ull b, ull c) {
    ull d; asm("fma.rn.f32x2 %0, %1, %2, %3;" : "=l"(d) : "l"(a), "l"(b), "l"(c));
    return d;
}

// ---------------------------------------------------------------------------
// Zero accumulators (graph replays reuse device state)
// ---------------------------------------------------------------------------
__global__ void zero_kernel() {
    int t = blockIdx.x * blockDim.x + threadIdx.x;   // 8192 threads
    g_s0[t]   = 0.f;
    g_S[0][t] = 0.f;
    g_S[1][t] = 0.f;
    if (t < 4) ((float*)g_Z)[t] = 0.f;
}

// ---------------------------------------------------------------------------
// Pass 0: s0[b,k,o] = sum_{r,i} x[b,r,i] * W[r,k,o,i]   (u_hat never stored)
// 512 threads = 128 b x 2 k x 2 o-halves. W staged to smem as [k][i][o]
// (f32x2-pair friendly), double buffered. Warp = 32 b's sharing (k,oh)
// -> every W LDS is a 32-lane broadcast.
// ---------------------------------------------------------------------------
__global__ __launch_bounds__(512, 2) void pass0_kernel(const float* __restrict__ x,
                                                       const float* __restrict__ W) {
    __shared__ __align__(16) float sw[2][2 * II * OO];   // [buf][k*512 + i*32 + o]
    const int t  = threadIdx.x;
    const int b  = t & 127;
    const int oh = (t >> 7) & 1;
    const int k  = t >> 8;
    const int r0 = blockIdx.x * NR;

    // W-loader mapping: 2 floats per thread; f = k*512 + o*16 + i
    const int lf = t * 2;
    const int lk = lf >> 9, lo = (lf >> 4) & 31, li = lf & 15;
    const int sidx = (lk * 16 + li) * 32 + lo;

    ull S2[8];
    #pragma unroll
    for (int q = 0; q < 8; q++) S2[q] = 0ull;

    // prologue: x(r0), W(r0)
    float4 xv[4];
    {
        const float4* xp = (const float4*)(x + ((size_t)b * RR + r0) * II);
        #pragma unroll
        for (int j = 0; j < 4; j++) xv[j] = xp[j];
    }
    {
        float2 w0 = *(const float2*)(W + (size_t)r0 * 1024 + lf);
        sw[0][sidx] = w0.x; sw[0][sidx + 32] = w0.y;
    }
    __syncthreads();

    for (int rr = 0; rr < NR; ++rr) {
        const int cur = rr & 1, nxt = cur ^ 1;
        const int r = r0 + rr;
        float2 wreg;
        if (rr + 1 < NR) wreg = *(const float2*)(W + (size_t)(r + 1) * 1024 + lf);

        const float* wb = &sw[cur][k * 512 + oh * 16];
        const float* xs = (const float*)xv;
        #pragma unroll
        for (int i = 0; i < II; i++) {
            ull xi2 = pack2(xs[i], xs[i]);
            const float* wrow = wb + i * 32;
            #pragma unroll
            for (int q = 0; q < 4; q++) {
                ulonglong2 w = *(const ulonglong2*)(wrow + q * 4);
                S2[2 * q]     = fma2(w.x, xi2, S2[2 * q]);
                S2[2 * q + 1] = fma2(w.y, xi2, S2[2 * q + 1]);
            }
        }
        // prefetch x for next r (xv dead after the i-loop)
        if (rr + 1 < NR) {
            const float4* xp = (const float4*)(x + ((size_t)b * RR + r + 1) * II);
            #pragma unroll
            for (int j = 0; j < 4; j++) xv[j] = xp[j];
        }
        if (rr + 1 < NR) { sw[nxt][sidx] = wreg.x; sw[nxt][sidx + 32] = wreg.y; }
        __syncthreads();
    }

    float* sp = g_s0 + b * KO + k * 32 + oh * 16;
    #pragma unroll
    for (int q = 0; q < 8; q++) {
        float lo2, hi2; unpack2(S2[q], lo2, hi2);
        atomicAdd(sp + 2 * q, lo2);
        atomicAdd(sp + 2 * q + 1, hi2);
    }
}

// ---------------------------------------------------------------------------
// Fused routing pass with on-the-fly u_hat recompute (deferred softmax):
//   u[b,r,k,o] = sum_i W[r,k,o,i] x[b,r,i]          (regs, from smem W)
//   a[r,k] = (1/B) sum_{b,o} u * v[b,k,o]
//   bnew = bprev + a ; e = exp(bnew)
//   Z[k] += e ; S[b,k,o] += e * u
// ---------------------------------------------------------------------------
__global__ __launch_bounds__(512, 1) void routing_kernel(const float* __restrict__ x,
                                                         const float* __restrict__ W,
                                                         int pass) {
    __shared__ __align__(16) float sw[2][2 * II * OO];
    __shared__ float red[16];
    __shared__ float ebc[2];
    const int t    = threadIdx.x;
    const int b    = t & 127;
    const int oh   = (t >> 7) & 1;
    const int k    = t >> 8;
    const int warp = t >> 5;
    const int lane = t & 31;
    const int r0   = blockIdx.x * NR;

    const int lf = t * 2;
    const int lk = lf >> 9, lo = (lf >> 4) & 31, li = lf & 15;
    const int sidx = (lk * 16 + li) * 32 + lo;

    // v for this (b,k,oh) into regs as f32x2
    ull v2[8];
    {
        const float4* vp = (const float4*)(g_v[pass] + b * KO + k * 32 + oh * 16);
        #pragma unroll
        for (int j = 0; j < 4; j++) {
            float4 q = vp[j];
            v2[2 * j]     = pack2(q.x, q.y);
            v2[2 * j + 1] = pack2(q.z, q.w);
        }
    }
    ull S2[8];
    #pragma unroll
    for (int q = 0; q < 8; q++) S2[q] = 0ull;
    float zacc = 0.f;

    float4 xv[4];
    {
        const float4* xp = (const float4*)(x + ((size_t)b * RR + r0) * II);
        #pragma unroll
        for (int j = 0; j < 4; j++) xv[j] = xp[j];
    }
    {
        float2 w0 = *(const float2*)(W + (size_t)r0 * 1024 + lf);
        sw[0][sidx] = w0.x; sw[0][sidx + 32] = w0.y;
    }
    __syncthreads();

    for (int rr = 0; rr < NR; ++rr) {
        const int cur = rr & 1, nxt = cur ^ 1;
        const int r = r0 + rr;
        float2 wreg;
        if (rr + 1 < NR) wreg = *(const float2*)(W + (size_t)(r + 1) * 1024 + lf);

        // ---- u_hat recompute (16 o per thread as 8 f32x2) ----
        ull u2[8];
        #pragma unroll
        for (int q = 0; q < 8; q++) u2[q] = 0ull;
        const float* wb = &sw[cur][k * 512 + oh * 16];
        const float* xs = (const float*)xv;
        #pragma unroll
        for (int i = 0; i < II; i++) {
            ull xi2 = pack2(xs[i], xs[i]);
            const float* wrow = wb + i * 32;
            #pragma unroll
            for (int q = 0; q < 4; q++) {
                ulonglong2 w = *(const ulonglong2*)(wrow + q * 4);
                u2[2 * q]     = fma2(w.x, xi2, u2[2 * q]);
                u2[2 * q + 1] = fma2(w.y, xi2, u2[2 * q + 1]);
            }
        }
        // prefetch x for next r
        if (rr + 1 < NR) {
            const float4* xp = (const float4*)(x + ((size_t)b * RR + r + 1) * II);
            #pragma unroll
            for (int j = 0; j < 4; j++) xv[j] = xp[j];
        }

        // ---- agreement dot ----
        ull d2 = 0ull;
        #pragma unroll
        for (int q = 0; q < 8; q++) d2 = fma2(u2[q], v2[q], d2);
        float dl, dh; unpack2(d2, dl, dh);
        float dot = dl + dh;
        #pragma unroll
        for (int m = 16; m >= 1; m >>= 1) dot += __shfl_xor_sync(0xffffffffu, dot, m);
        if (lane == 0) red[warp] = dot;
        __syncthreads();                      // A: red ready

        if (t < 2) {                          // t == k
            float a = 0.f;
            #pragma unroll
            for (int w = 0; w < 8; w++) a += red[t * 8 + w];
            a *= INV_B;
            float bn = a;
            if (pass == 1) bn += g_b1[(size_t)r * 2 + t];
            else           g_b1[(size_t)r * 2 + t] = bn;
            ebc[t] = expf(bn);
        }
        if (rr + 1 < NR) { sw[nxt][sidx] = wreg.x; sw[nxt][sidx + 32] = wreg.y; }
        __syncthreads();                      // B: ebc + next W ready

        const float e = ebc[k];
        if ((t & 255) == 0) zacc += e;        // t==0 (k=0), t==256 (k=1)
        ull e2 = pack2(e, e);
        #pragma unroll
        for (int q = 0; q < 8; q++) S2[q] = fma2(u2[q], e2, S2[q]);
    }

    float* sp = g_S[pass] + b * KO + k * 32 + oh * 16;
    #pragma unroll
    for (int q = 0; q < 8; q++) {
        float lo2, hi2; unpack2(S2[q], lo2, hi2);
        atomicAdd(sp + 2 * q, lo2);
        atomicAdd(sp + 2 * q + 1, hi2);
    }
    if ((t & 255) == 0) atomicAdd(&g_Z[pass][k], zacc);
}

// ---------------------------------------------------------------------------
// Squash: one warp per (b,k); lane = o.
// mode 0: v0 = squash(s0/R); mode 1: v1 = squash(S0/Z0); mode 2: out = squash(S1/Z1)
// ---------------------------------------------------------------------------
__global__ void squash_kernel(int mode, float* __restrict__ out) {
    const int t = blockIdx.x * blockDim.x + threadIdx.x;  // 8192
    const int k = (t >> 5) & 1;
    float s;
    if (mode == 0) {
        s = g_s0[t] * INV_R;
    } else {
        const int p = mode - 1;
        s = g_S[p][t] / g_Z[p][k];
    }
    float sq = s * s;
    #pragma unroll
    for (int m = 16; m >= 1; m >>= 1) sq += __shfl_xor_sync(0xffffffffu, sq, m);
    const float sn = sq;
    const float f = sqrtf(sn) / (0.5f + sn);
    const float v = s * f;
    if (mode == 2) out[t] = v;
    else           g_v[mode][t] = v;
}

// ---------------------------------------------------------------------------
extern "C" void kernel_launch(void* const* d_in, const int* in_sizes, int n_in,
                              void* d_out, int out_size) {
    const float* x = (const float*)d_in[0];   // [128, 4608, 16]
    const float* W = (const float*)d_in[1];   // [1, 4608, 2, 32, 16]
    float* out = (float*)d_out;               // [128, 2, 32]

    zero_kernel<<<32, 256>>>();
    pass0_kernel<<<NCTA, 512>>>(x, W);        // s0 (no u_hat materialization)
    squash_kernel<<<32, 256>>>(0, nullptr);   // v0
    routing_kernel<<<NCTA, 512>>>(x, W, 0);   // a0 -> b1 -> S1, Z1
    squash_kernel<<<32, 256>>>(1, nullptr);   // v1
    routing_kernel<<<NCTA, 512>>>(x, W, 1);   // a1 -> b2 -> S2, Z2
    squash_kernel<<<32, 256>>>(2, out);       // v2 -> output
}